// round 8
// baseline (speedup 1.0000x reference)
#include <cuda_runtime.h>
#include <math.h>

#define NSPEC  256
#define NSPEC3 5456
#define NPACK  2856   // sum over l of (2l+1)*(l+1)  — only nloc >= l kept

typedef unsigned long long ull;

// scratch (static device globals — allowed)
__device__ float2 g_fhat [16*16*NSPEC];     // [b][f][s]
__device__ float2 g_psi  [16*64*NSPEC];     // [i][o][s]
__device__ float2 g_Fz   [1024*NPACK];      // [b*64+o][packed e]  (23.4 MB)
__device__ float2 g_wig3p[32*NPACK];        // packed wig_so3, duplicated (d,d) for FFMA2
__device__ int    g_lut  [NPACK];           // packed (sm_ << 16) | sn for k_fz

__constant__ int c_offs[16] = {0,1,10,35,84,165,286,455,680,969,1330,1771,2300,2925,3654,4495};
__constant__ int c_offP[16] = {0,1,7,22,50,95,161,252,372,525,715,946,1222,1547,1925,2360};
// c_step[l] = (2l+3)(l+1): idx_{l+1} = idx_l + c_step[l] + m
__constant__ int c_step[15] = {3,10,21,36,55,78,105,136,171,210,253,300,351,406,465};

// packed fp32 FMA (sm_103a FFMA2) — only reachable via PTX
__device__ __forceinline__ ull fma2(ull a, ull b, ull c) {
    ull d;
    asm("fma.rn.f32x2 %0, %1, %2, %3;" : "=l"(d) : "l"(a), "l"(b), "l"(c));
    return d;
}
__device__ __forceinline__ float2 u2f(ull u) {
    float2 v;
    asm("mov.b64 {%0,%1}, %2;" : "=f"(v.x), "=f"(v.y) : "l"(u));
    return v;
}

// ---------------- Kernel 1: fhat[b,f,s] (Hermitian fold: DFT only for m>=0) ----------------
__global__ void k_fhat(const float* __restrict__ x, const float* __restrict__ wig) {
    __shared__ float  sx[64*65];
    __shared__ float2 xf[64*16];       // [j][m], m = 0..15
    __shared__ float2 cs64[64];        // e^{-2pi i t/64}
    int b = blockIdx.x, f = blockIdx.y, tid = threadIdx.x;
    if (tid < 64) { float sv, cv; sincospif((float)tid/32.0f, &sv, &cv); cs64[tid] = make_float2(cv, -sv); }
    const float* xp = x + (size_t)(b*16+f)*4096;
    for (int p = tid; p < 4096; p += 256) sx[(p>>6)*65 + (p&63)] = xp[p];
    __syncthreads();
    for (int p = tid; p < 1024; p += 256) {           // 16 m-values (0..15) x 64 betas
        int m = p >> 6, j = p & 63;
        float ar=0.f, ai=0.f;
        const float* row = &sx[j*65];
        int t = 0;
        #pragma unroll 8
        for (int a = 0; a < 64; a++) {
            float2 e = cs64[t];                        // broadcast
            float v = row[a];
            ar += v*e.x;
            ai += v*e.y;
            t = (t + m) & 63;
        }
        xf[j*16+m] = make_float2(ar, ai);
    }
    __syncthreads();
    int s = tid;
    int l = (int)sqrtf((float)s);
    while ((l+1)*(l+1) <= s) ++l;
    while (l*l > s) --l;
    int m = s - l*l - l;
    int am = m < 0 ? -m : m;
    float sgn = m < 0 ? -1.f : 1.f;                    // xf[-m] = conj(xf[m])
    float ar=0.f, ai=0.f;
    #pragma unroll 8
    for (int j = 0; j < 64; j++) {
        float w = wig[j*NSPEC + s];
        float2 v = xf[j*16+am];
        ar += w*v.x; ai += w*v.y;
    }
    g_fhat[(b*16+f)*NSPEC + s] = make_float2(ar, sgn*ai);
}

// ---------------- Kernel 2: psi[i,o,s] = scaling * sum_g kernel[i,o,g] * Fk[s,g] ----------------
__global__ void k_psi(const float* __restrict__ kern, const float* __restrict__ fkr,
                      const float* __restrict__ fki, float scaling) {
    __shared__ float2 fk[32];
    int s = blockIdx.x, tid = threadIdx.x;
    if (tid < 32) fk[tid] = make_float2(fkr[s*32+tid]*scaling, fki[s*32+tid]*scaling);
    __syncthreads();
    for (int p = tid; p < 1024; p += 256) {            // p = i*64+o
        const float* kp = kern + p*32;
        float ar=0.f, ai=0.f;
        #pragma unroll
        for (int g = 0; g < 32; g++) { float kv = kp[g]; ar += kv*fk[g].x; ai += kv*fk[g].y; }
        g_psi[p*NSPEC + s] = make_float2(ar, ai);
    }
}

// ---------------- Kernel 2b: pack wig_so3 (duplicated for FFMA2) + build k_fz index LUT ----------------
__global__ void k_pack(const float* __restrict__ wig3) {
    int k = blockIdx.x, tid = threadIdx.x;
    for (int p = tid; p < NPACK; p += 256) {
        int l = 15;
        while (c_offP[l] > p) --l;
        int r = p - c_offP[l];
        int mloc = r / (l+1);
        int nq   = r - mloc*(l+1);
        float v = wig3[k*NSPEC3 + c_offs[l] + mloc*(2*l+1) + (nq + l)];
        g_wig3p[k*NPACK + p] = make_float2(v, v);
        if (k == 0) {
            int sm_ = l*l + mloc;
            int sn  = l*l + nq + l;
            g_lut[p] = (sm_ << 16) | sn;
        }
    }
}

// ---------------- Kernel 3: packed Fz (only n >= 0), conflict-free [i][s] smem layout ----------------
__global__ void k_fz() {
    extern __shared__ float2 sm3[];
    float2* fh = sm3;          // [i*256+s]
    float2* ps = sm3 + 4096;   // [i*256+s]
    int bo = blockIdx.x, b = bo >> 6, o = bo & 63, tid = threadIdx.x;
    for (int p = tid; p < 4096; p += 512) {
        int i = p >> 8, s = p & 255;
        fh[p] = g_fhat[(b*16+i)*NSPEC + s];            // coalesced
        ps[p] = g_psi [(i*64+o)*NSPEC + s];            // coalesced
    }
    __syncthreads();
    for (int e = tid; e < NPACK; e += 512) {
        int lu = __ldg(&g_lut[e]);
        int sm_ = lu >> 16, sn = lu & 0xffff;
        float ar=0.f, ai=0.f;
        #pragma unroll
        for (int i = 0; i < 16; i++) {
            float2 a = fh[i*256 + sm_];
            float2 c = ps[i*256 + sn];
            ar += a.x*c.x + a.y*c.y;                   // fhat * conj(psi)
            ai += a.y*c.x - a.x*c.y;
        }
        g_Fz[(size_t)bo*NPACK + e] = make_float2(ar, ai);
    }
}

// ---------------- Kernel 4 (fused, Hermitian + radix-4, dual-k, FFMA2) ----------------
// grid (1024 bo, 4 kq); each block handles 8 beta_out values, 2 at a time.
// smem: Fz 2856 f2 | spc 1024 f2 | Vv 1024 f2 | cs4a 248 f4 (c,c,s,s) | cs2b 240 f2
// total = 22848 + 8192 + 8192 + 3968 + 1920 = 45120 B -> 5 CTAs/SM
__global__ void k_main(const float* __restrict__ bias, float* __restrict__ out) {
    extern __shared__ float smraw[];
    float2* Fz   = (float2*)smraw;          // 2856
    float2* spc  = Fz  + 2856;              // 1024: [kp*512 + mi*16 + nq]
    float2* Vv   = spc + 1024;              // 1024: [kp*512 + a*16 + nq]
    float4* cs4a = (float4*)(Vv + 1024);    // 248:  [mi*8 + a0] = (c,c,s,s), t=((mi-15)a0)&31
    float2* cs2b = (float2*)(cs4a + 248);   // 240:  [(n-1)*16 + lo] = (cos,sin), t=(n*lo)&31
    int tid = threadIdx.x;
    int bo = blockIdx.x, o = bo & 63;
    int kq = blockIdx.y;

    for (int p = tid; p < 248; p += 256) {
        int mi = p >> 3, a0 = p & 7;
        int t = ((mi-15)*a0) & 31;
        float sv, cv; sincospif((float)t / 16.0f, &sv, &cv);
        cs4a[p] = make_float4(cv, cv, sv, sv);
    }
    if (tid < 240) {
        int n = (tid >> 4) + 1, lo = tid & 15;
        int t = (n*lo) & 31;
        float sv, cv; sincospif((float)t / 16.0f, &sv, &cv);
        cs2b[tid] = make_float2(cv, sv);
    }
    for (int p = tid; p < NPACK; p += 256) Fz[p] = g_Fz[(size_t)bo*NPACK + p];
    float bv = bias[o];

    int kp = tid >> 7, t2 = tid & 127;

    for (int kk4 = 0; kk4 < 4; kk4++) {
        int k = kq*8 + kk4*2 + kp;
        __syncthreads();                               // prior stage2 done before spc/Vv rewrite

        // spec[m,n] for n>=0 (half-block per k-plane); packed FFMA2 with dup'd wigner
        const ull* wkgU = (const ull*)(g_wig3p + k*NPACK);
        const ull* FzU  = (const ull*)Fz;
        for (int p = t2; p < 496; p += 128) {
            int mi = p >> 4, nq = p & 15;
            int m = mi - 15;
            int am = m < 0 ? -m : m;
            int lmin = am > nq ? am : nq;
            ull acc = 0ull;
            int idx = c_offP[lmin] + (m+lmin)*(lmin+1) + nq;
            for (int l = lmin; l < 16; l++) {
                ull d2 = __ldg(&wkgU[idx]);
                acc = fma2(FzU[idx], d2, acc);
                if (l < 15) idx += c_step[l] + m;
            }
            spc[kp*512 + p] = u2f(acc);
        }
        __syncthreads();

        // stage 1 (radix-4 over m, FFMA2 deferred combine): 31 terms -> V[a0],V[a0+8],V[a0+16],V[a0+24]
        {
            int a0 = t2 >> 4, n = t2 & 15;             // a0 in 0..7
            const ull* spU = (const ull*)(spc + kp*512);
            const ulonglong2* e4 = (const ulonglong2*)cs4a;
            ull A0=0,A1=0,A2=0,A3=0,B0=0,B1=0,B2=0,B3=0;
            #pragma unroll
            for (int mi = 0; mi < 31; mi++) {
                ull sp = spU[mi*16 + n];
                ulonglong2 e = e4[mi*8 + a0];          // e.x=(c,c), e.y=(s,s)
                const int r = (mi + 1) & 3;            // (mi-15) mod 4, compile-time
                if      (r == 0) { A0 = fma2(sp, e.x, A0); B0 = fma2(sp, e.y, B0); }
                else if (r == 1) { A1 = fma2(sp, e.x, A1); B1 = fma2(sp, e.y, B1); }
                else if (r == 2) { A2 = fma2(sp, e.x, A2); B2 = fma2(sp, e.y, B2); }
                else             { A3 = fma2(sp, e.x, A3); B3 = fma2(sp, e.y, B3); }
            }
            float2 a0f=u2f(A0), b0f=u2f(B0), a1f=u2f(A1), b1f=u2f(B1);
            float2 a2f=u2f(A2), b2f=u2f(B2), a3f=u2f(A3), b3f=u2f(B3);
            float s0r = a0f.x - b0f.y, s0i = a0f.y + b0f.x;
            float s1r = a1f.x - b1f.y, s1i = a1f.y + b1f.x;
            float s2r = a2f.x - b2f.y, s2i = a2f.y + b2f.x;
            float s3r = a3f.x - b3f.y, s3i = a3f.y + b3f.x;
            float2* V = Vv + kp*512;
            V[(a0     )*16 + n] = make_float2(s0r + s1r + s2r + s3r,  s0i + s1i + s2i + s3i);
            V[(a0 +  8)*16 + n] = make_float2(s0r - s1i - s2r + s3i,  s0i + s1r - s2i - s3r);
            V[(a0 + 16)*16 + n] = make_float2(s0r - s1r + s2r - s3r,  s0i - s1i + s2i - s3i);
            V[(a0 + 24)*16 + n] = make_float2(s0r + s1i - s2r - s3i,  s0i - s1r - s2i + s3r);
        }
        __syncthreads();

        // stage 2 (radix-2 over n, FFMA2 packed real-part): out[a][g], out[a][g+16]
        {
            int hi = t2 >> 4, lo = t2 & 15;            // hi in 0..7, g = lo
            const float2* V = Vv + kp*512;
            const ull* VU = (const ull*)V;
            const ull* eU = (const ull*)cs2b;
            size_t base = ((size_t)bo*32 + k)*1024;
            #pragma unroll
            for (int da = 0; da < 4; da++) {
                int a = hi*4 + da;
                ull Pe = 0ull, Po = 0ull;
                #pragma unroll
                for (int n = 1; n < 16; n++) {
                    ull v = VU[a*16 + n];              // broadcast
                    ull e = eU[(n-1)*16 + lo];         // (cos, sin)
                    if (n & 1) Po = fma2(v, e, Po); else Pe = fma2(v, e, Pe);
                }
                float2 pe = u2f(Pe), po = u2f(Po);
                float se = pe.x - pe.y, so = po.x - po.y;
                float c0 = bv + V[a*16].x;
                out[base + a*32 + lo     ] = c0 + 2.f*(se + so);
                out[base + a*32 + lo + 16] = c0 + 2.f*(se - so);
            }
        }
    }
}

extern "C" void kernel_launch(void* const* d_in, const int* in_sizes, int n_in,
                              void* d_out, int out_size) {
    const float* x       = (const float*)d_in[0];
    const float* kern    = (const float*)d_in[1];
    const float* bias    = (const float*)d_in[2];
    const float* wig_s2  = (const float*)d_in[3];
    const float* fk_re   = (const float*)d_in[4];
    const float* fk_im   = (const float*)d_in[5];
    const float* wig_so3 = (const float*)d_in[6];
    float* out = (float*)d_out;

    float scaling = 1.0f / sqrtf(32768.0f);

    cudaFuncSetAttribute(k_fz,   cudaFuncAttributeMaxDynamicSharedMemorySize, 65536);
    cudaFuncSetAttribute(k_main, cudaFuncAttributeMaxDynamicSharedMemorySize, 45120);

    k_fhat<<<dim3(16,16), 256>>>(x, wig_s2);
    k_psi <<<256, 256>>>(kern, fk_re, fk_im, scaling);
    k_pack<<<32, 256>>>(wig_so3);
    k_fz  <<<1024, 512, 65536>>>();
    k_main<<<dim3(1024, 4), 256, 45120>>>(bias, out);
}

// round 9
// speedup vs baseline: 1.1441x; 1.1441x over previous
#include <cuda_runtime.h>
#include <math.h>

#define NSPEC  256
#define NSPEC3 5456
#define NPACK  2856   // sum over l of (2l+1)*(l+1)  — only nloc >= l kept

// scratch (static device globals — allowed)
__device__ float2 g_fhat [16*16*NSPEC];     // [b][f][s]
__device__ float2 g_psi  [16*64*NSPEC];     // [i][o][s]
__device__ float2 g_Fz   [1024*NPACK];      // [b*64+o][packed e]  (23.4 MB)
__device__ float  g_wig3p[32*NPACK];        // packed wig_so3
__device__ int    g_lut  [NPACK];           // packed (sm_ << 16) | sn for k_fz

__constant__ int c_offs[16] = {0,1,10,35,84,165,286,455,680,969,1330,1771,2300,2925,3654,4495};
__constant__ int c_offP[16] = {0,1,7,22,50,95,161,252,372,525,715,946,1222,1547,1925,2360};
// c_step[l] = (2l+3)(l+1): idx_{l+1} = idx_l + c_step[l] + m
__constant__ int c_step[15] = {3,10,21,36,55,78,105,136,171,210,253,300,351,406,465};

// ---------------- Kernel 1: fhat[b,f,s] (Hermitian fold: DFT only for m>=0) ----------------
__global__ void k_fhat(const float* __restrict__ x, const float* __restrict__ wig) {
    __shared__ float  sx[64*65];
    __shared__ float2 xf[64*16];       // [j][m], m = 0..15
    __shared__ float2 cs64[64];        // e^{-2pi i t/64}
    int b = blockIdx.x, f = blockIdx.y, tid = threadIdx.x;
    if (tid < 64) { float sv, cv; sincospif((float)tid/32.0f, &sv, &cv); cs64[tid] = make_float2(cv, -sv); }
    const float* xp = x + (size_t)(b*16+f)*4096;
    for (int p = tid; p < 4096; p += 256) sx[(p>>6)*65 + (p&63)] = xp[p];
    __syncthreads();
    for (int p = tid; p < 1024; p += 256) {           // 16 m-values (0..15) x 64 betas
        int m = p >> 6, j = p & 63;
        float ar=0.f, ai=0.f;
        const float* row = &sx[j*65];
        int t = 0;
        #pragma unroll 8
        for (int a = 0; a < 64; a++) {
            float2 e = cs64[t];                        // broadcast
            float v = row[a];
            ar += v*e.x;
            ai += v*e.y;
            t = (t + m) & 63;
        }
        xf[j*16+m] = make_float2(ar, ai);
    }
    __syncthreads();
    int s = tid;
    int l = (int)sqrtf((float)s);
    while ((l+1)*(l+1) <= s) ++l;
    while (l*l > s) --l;
    int m = s - l*l - l;
    int am = m < 0 ? -m : m;
    float sgn = m < 0 ? -1.f : 1.f;                    // xf[-m] = conj(xf[m])
    float ar=0.f, ai=0.f;
    #pragma unroll 8
    for (int j = 0; j < 64; j++) {
        float w = wig[j*NSPEC + s];
        float2 v = xf[j*16+am];
        ar += w*v.x; ai += w*v.y;
    }
    g_fhat[(b*16+f)*NSPEC + s] = make_float2(ar, sgn*ai);
}

// ---------------- Kernel 2: psi[i,o,s] = scaling * sum_g kernel[i,o,g] * Fk[s,g] ----------------
__global__ void k_psi(const float* __restrict__ kern, const float* __restrict__ fkr,
                      const float* __restrict__ fki, float scaling) {
    __shared__ float2 fk[32];
    int s = blockIdx.x, tid = threadIdx.x;
    if (tid < 32) fk[tid] = make_float2(fkr[s*32+tid]*scaling, fki[s*32+tid]*scaling);
    __syncthreads();
    for (int p = tid; p < 1024; p += 256) {            // p = i*64+o
        const float* kp = kern + p*32;
        float ar=0.f, ai=0.f;
        #pragma unroll
        for (int g = 0; g < 32; g++) { float kv = kp[g]; ar += kv*fk[g].x; ai += kv*fk[g].y; }
        g_psi[p*NSPEC + s] = make_float2(ar, ai);
    }
}

// ---------------- Kernel 2b: pack wig_so3 to nloc>=l layout + build k_fz index LUT ----------------
__global__ void k_pack(const float* __restrict__ wig3) {
    int k = blockIdx.x, tid = threadIdx.x;
    for (int p = tid; p < NPACK; p += 256) {
        int l = 15;
        while (c_offP[l] > p) --l;
        int r = p - c_offP[l];
        int mloc = r / (l+1);
        int nq   = r - mloc*(l+1);
        g_wig3p[k*NPACK + p] = wig3[k*NSPEC3 + c_offs[l] + mloc*(2*l+1) + (nq + l)];
        if (k == 0) {
            int sm_ = l*l + mloc;
            int sn  = l*l + nq + l;
            g_lut[p] = (sm_ << 16) | sn;
        }
    }
}

// ---------------- Kernel 3: packed Fz (only n >= 0), conflict-free [i][s] smem layout ----------------
__global__ void k_fz() {
    extern __shared__ float2 sm3[];
    float2* fh = sm3;          // [i*256+s]
    float2* ps = sm3 + 4096;   // [i*256+s]
    int bo = blockIdx.x, b = bo >> 6, o = bo & 63, tid = threadIdx.x;
    for (int p = tid; p < 4096; p += 512) {
        int i = p >> 8, s = p & 255;
        fh[p] = g_fhat[(b*16+i)*NSPEC + s];            // coalesced
        ps[p] = g_psi [(i*64+o)*NSPEC + s];            // coalesced
    }
    __syncthreads();
    for (int e = tid; e < NPACK; e += 512) {
        int lu = __ldg(&g_lut[e]);
        int sm_ = lu >> 16, sn = lu & 0xffff;
        float ar=0.f, ai=0.f;
        #pragma unroll
        for (int i = 0; i < 16; i++) {
            float2 a = fh[i*256 + sm_];
            float2 c = ps[i*256 + sn];
            ar += a.x*c.x + a.y*c.y;                   // fhat * conj(psi)
            ai += a.y*c.x - a.x*c.y;
        }
        g_Fz[(size_t)bo*NPACK + e] = make_float2(ar, ai);
    }
}

// ---------------- Kernel 4 (fused, Hermitian + radix-4, dual-k): spec(n>=0) + 2D synthesis ----------------
// grid (1024 bo, 4 kq); each block handles 8 beta_out values, 2 at a time.
// smem float2 units: Fz 2856 | spc 1024 (2x512) | Vv 1024 (2x512) | cs16 496
// total = (2856+1024+1024+496)*8 = 43200 B -> 5 CTAs/SM
__global__ void k_main(const float* __restrict__ bias, float* __restrict__ out) {
    extern __shared__ float smraw[];
    float2* Fz   = (float2*)smraw;     // 2856
    float2* spc  = Fz  + 2856;         // 1024: [kp*512 + mi*16 + nq]
    float2* Vv   = spc + 1024;         // 1024: [kp*512 + a*16 + nq]
    float2* cs16 = Vv  + 1024;         // 496:  cs16[q*16+r] = e^{+2pi i (q-15) r/32}, r<16
    int tid = threadIdx.x;
    int bo = blockIdx.x, o = bo & 63;
    int kq = blockIdx.y;

    for (int p = tid; p < 496; p += 256) {
        int q = p >> 4, r = p & 15;
        int t = ((q-15)*r) & 31;
        float sv, cv; sincospif((float)t / 16.0f, &sv, &cv);
        cs16[p] = make_float2(cv, sv);
    }
    for (int p = tid; p < NPACK; p += 256) Fz[p] = g_Fz[(size_t)bo*NPACK + p];
    float bv = bias[o];

    int kp = tid >> 7, t2 = tid & 127;

    for (int kk4 = 0; kk4 < 4; kk4++) {
        int k = kq*8 + kk4*2 + kp;
        __syncthreads();                               // prior stage2 done before spc/Vv rewrite

        // spec[m,n] for n>=0 (half-block per k-plane), incremental packed index
        const float* wkg = g_wig3p + k*NPACK;
        for (int p = t2; p < 496; p += 128) {
            int mi = p >> 4, nq = p & 15;
            int m = mi - 15;
            int am = m < 0 ? -m : m;
            int lmin = am > nq ? am : nq;
            float ar = 0.f, ai = 0.f;
            int idx = c_offP[lmin] + (m+lmin)*(lmin+1) + nq;
            for (int l = lmin; l < 16; l++) {
                float d = __ldg(&wkg[idx]);
                float2 fz = Fz[idx];
                ar = fmaf(fz.x, d, ar);
                ai = fmaf(fz.y, d, ai);
                if (l < 15) idx += c_step[l] + m;
            }
            spc[kp*512 + p] = make_float2(ar, ai);
        }
        __syncthreads();

        // stage 1 (radix-4 over m, direct chained-FMA accumulation into 8 class regs)
        {
            int a0 = t2 >> 4, n = t2 & 15;             // a0 in 0..7
            float s0r=0,s0i=0,s1r=0,s1i=0,s2r=0,s2i=0,s3r=0,s3i=0;
            #pragma unroll
            for (int mi = 0; mi < 31; mi++) {
                float2 sp = spc[kp*512 + mi*16 + n];
                float2 e  = cs16[mi*16 + a0];          // e^{+2pi i (mi-15) a0/32}
                const int r = (mi + 1) & 3;            // (mi-15) mod 4, compile-time
                if (r == 0) {
                    s0r = fmaf(sp.x, e.x, s0r); s0r = fmaf(-sp.y, e.y, s0r);
                    s0i = fmaf(sp.x, e.y, s0i); s0i = fmaf( sp.y, e.x, s0i);
                } else if (r == 1) {
                    s1r = fmaf(sp.x, e.x, s1r); s1r = fmaf(-sp.y, e.y, s1r);
                    s1i = fmaf(sp.x, e.y, s1i); s1i = fmaf( sp.y, e.x, s1i);
                } else if (r == 2) {
                    s2r = fmaf(sp.x, e.x, s2r); s2r = fmaf(-sp.y, e.y, s2r);
                    s2i = fmaf(sp.x, e.y, s2i); s2i = fmaf( sp.y, e.x, s2i);
                } else {
                    s3r = fmaf(sp.x, e.x, s3r); s3r = fmaf(-sp.y, e.y, s3r);
                    s3i = fmaf(sp.x, e.y, s3i); s3i = fmaf( sp.y, e.x, s3i);
                }
            }
            float2* V = Vv + kp*512;
            V[(a0     )*16 + n] = make_float2(s0r + s1r + s2r + s3r,  s0i + s1i + s2i + s3i);
            V[(a0 +  8)*16 + n] = make_float2(s0r - s1i - s2r + s3i,  s0i + s1r - s2i - s3r);
            V[(a0 + 16)*16 + n] = make_float2(s0r - s1r + s2r - s3r,  s0i - s1i + s2i - s3i);
            V[(a0 + 24)*16 + n] = make_float2(s0r + s1i - s2r - s3i,  s0i - s1r - s2i + s3r);
        }
        __syncthreads();

        // stage 2 (radix-2 over n, n-outer loop: e loaded once per n, shared by 4 a-values)
        {
            int hi = t2 >> 4, lo = t2 & 15;            // hi in 0..7, g = lo
            const float2* V = Vv + kp*512;
            int a0 = hi*4;
            float se0=0,so0=0,se1=0,so1=0,se2=0,so2=0,se3=0,so3=0;
            #pragma unroll
            for (int n = 1; n < 16; n++) {
                float2 e = cs16[(n+15)*16 + lo];       // e^{+2pi i n g/32}, 1 load per n
                float2 v0 = V[(a0+0)*16 + n];
                float2 v1 = V[(a0+1)*16 + n];
                float2 v2 = V[(a0+2)*16 + n];
                float2 v3 = V[(a0+3)*16 + n];
                if (n & 1) {
                    so0 = fmaf(v0.x, e.x, so0); so0 = fmaf(-v0.y, e.y, so0);
                    so1 = fmaf(v1.x, e.x, so1); so1 = fmaf(-v1.y, e.y, so1);
                    so2 = fmaf(v2.x, e.x, so2); so2 = fmaf(-v2.y, e.y, so2);
                    so3 = fmaf(v3.x, e.x, so3); so3 = fmaf(-v3.y, e.y, so3);
                } else {
                    se0 = fmaf(v0.x, e.x, se0); se0 = fmaf(-v0.y, e.y, se0);
                    se1 = fmaf(v1.x, e.x, se1); se1 = fmaf(-v1.y, e.y, se1);
                    se2 = fmaf(v2.x, e.x, se2); se2 = fmaf(-v2.y, e.y, se2);
                    se3 = fmaf(v3.x, e.x, se3); se3 = fmaf(-v3.y, e.y, se3);
                }
            }
            size_t base = ((size_t)bo*32 + k)*1024;
            float c0 = bv + V[(a0+0)*16].x;
            float c1 = bv + V[(a0+1)*16].x;
            float c2 = bv + V[(a0+2)*16].x;
            float c3 = bv + V[(a0+3)*16].x;
            out[base + (a0+0)*32 + lo     ] = c0 + 2.f*(se0 + so0);
            out[base + (a0+0)*32 + lo + 16] = c0 + 2.f*(se0 - so0);
            out[base + (a0+1)*32 + lo     ] = c1 + 2.f*(se1 + so1);
            out[base + (a0+1)*32 + lo + 16] = c1 + 2.f*(se1 - so1);
            out[base + (a0+2)*32 + lo     ] = c2 + 2.f*(se2 + so2);
            out[base + (a0+2)*32 + lo + 16] = c2 + 2.f*(se2 - so2);
            out[base + (a0+3)*32 + lo     ] = c3 + 2.f*(se3 + so3);
            out[base + (a0+3)*32 + lo + 16] = c3 + 2.f*(se3 - so3);
        }
    }
}

extern "C" void kernel_launch(void* const* d_in, const int* in_sizes, int n_in,
                              void* d_out, int out_size) {
    const float* x       = (const float*)d_in[0];
    const float* kern    = (const float*)d_in[1];
    const float* bias    = (const float*)d_in[2];
    const float* wig_s2  = (const float*)d_in[3];
    const float* fk_re   = (const float*)d_in[4];
    const float* fk_im   = (const float*)d_in[5];
    const float* wig_so3 = (const float*)d_in[6];
    float* out = (float*)d_out;

    float scaling = 1.0f / sqrtf(32768.0f);

    cudaFuncSetAttribute(k_fz,   cudaFuncAttributeMaxDynamicSharedMemorySize, 65536);
    cudaFuncSetAttribute(k_main, cudaFuncAttributeMaxDynamicSharedMemorySize, 43200);

    k_fhat<<<dim3(16,16), 256>>>(x, wig_s2);
    k_psi <<<256, 256>>>(kern, fk_re, fk_im, scaling);
    k_pack<<<32, 256>>>(wig_so3);
    k_fz  <<<1024, 512, 65536>>>();
    k_main<<<dim3(1024, 4), 256, 43200>>>(bias, out);
}

// round 10
// speedup vs baseline: 1.2599x; 1.1011x over previous
#include <cuda_runtime.h>
#include <math.h>

#define NSPEC  256
#define NSPEC3 5456
#define NPACK  2856   // sum over l of (2l+1)*(l+1)  — only nloc >= l kept

// scratch (static device globals — allowed)
__device__ float2 g_fhat [16*16*NSPEC];     // [b][f][s]
__device__ float2 g_psi  [16*64*NSPEC];     // [i][o][s]
__device__ float2 g_Fz   [1024*NPACK];      // [b*64+o][packed e]  (23.4 MB)
__device__ float  g_wig3p[32*NPACK];        // packed wig_so3
__device__ int    g_lut  [NPACK];           // packed (sm_ << 16) | sn for k_fz

__constant__ int c_offs[16] = {0,1,10,35,84,165,286,455,680,969,1330,1771,2300,2925,3654,4495};
__constant__ int c_offP[16] = {0,1,7,22,50,95,161,252,372,525,715,946,1222,1547,1925,2360};
// c_step[l] = (2l+3)(l+1): idx_{l+1} = idx_l + c_step[l] + m
__constant__ int c_step[15] = {3,10,21,36,55,78,105,136,171,210,253,300,351,406,465};

// ---------------- Kernel 1: fhat[b,f,s] (Hermitian fold over m + radix-2 fold over alpha) ----------------
// smem layout (floats): [0,4160)=sx (later aliased by xf float2), [4160,6272)=su, [6272,8384)=sv,
//                       [8384,8512)=cs64 (64 float2). Total 34048 B.
__global__ void k_fhat(const float* __restrict__ x, const float* __restrict__ wig) {
    __shared__ float buf[8512];
    float*  sx   = buf;                       // [j*65 + a], a<64
    float2* xf   = (float2*)buf;              // [j*16 + m], m<16 (aliases sx after it is dead)
    float*  su   = buf + 4160;                // [j*33 + a], a<32: x[a]+x[a+32]
    float*  sv   = buf + 6272;                // [j*33 + a], a<32: x[a]-x[a+32]
    float2* cs64 = (float2*)(buf + 8384);     // e^{-2pi i t/64}
    int b = blockIdx.x, f = blockIdx.y, tid = threadIdx.x;
    if (tid < 64) { float sv_, cv; sincospif((float)tid/32.0f, &sv_, &cv); cs64[tid] = make_float2(cv, -sv_); }
    const float* xp = x + (size_t)(b*16+f)*4096;
    for (int p = tid; p < 4096; p += 256) sx[(p>>6)*65 + (p&63)] = xp[p];
    __syncthreads();
    for (int p = tid; p < 2048; p += 256) {           // u/v fold: 64 j x 32 a
        int j = p >> 5, a = p & 31;
        float lo = sx[j*65 + a], hi = sx[j*65 + a + 32];
        su[j*33 + a] = lo + hi;
        sv[j*33 + a] = lo - hi;
    }
    __syncthreads();
    for (int p = tid; p < 1024; p += 256) {           // 16 m-values (0..15) x 64 betas, 32 iters
        int m = p >> 6, j = p & 63;
        const float* row = (m & 1) ? &sv[j*33] : &su[j*33];
        float ar=0.f, ai=0.f;
        int t = 0;
        #pragma unroll 8
        for (int a = 0; a < 32; a++) {
            float2 e = cs64[t];                        // broadcast
            float v = row[a];
            ar += v*e.x;
            ai += v*e.y;
            t = (t + m) & 63;
        }
        xf[j*16+m] = make_float2(ar, ai);              // overwrites dead sx region
    }
    __syncthreads();
    int s = tid;
    int l = (int)sqrtf((float)s);
    while ((l+1)*(l+1) <= s) ++l;
    while (l*l > s) --l;
    int m = s - l*l - l;
    int am = m < 0 ? -m : m;
    float sgn = m < 0 ? -1.f : 1.f;                    // xf[-m] = conj(xf[m])
    float ar=0.f, ai=0.f;
    #pragma unroll 8
    for (int j = 0; j < 64; j++) {
        float w = wig[j*NSPEC + s];
        float2 v = xf[j*16+am];
        ar += w*v.x; ai += w*v.y;
    }
    g_fhat[(b*16+f)*NSPEC + s] = make_float2(ar, sgn*ai);
}

// ---------------- Kernel 2 (merged): blocks 0..255 = psi, blocks 256..287 = pack wig_so3 + LUT ----------------
__global__ void k_prep(const float* __restrict__ kern, const float* __restrict__ fkr,
                       const float* __restrict__ fki, float scaling,
                       const float* __restrict__ wig3) {
    int tid = threadIdx.x;
    if (blockIdx.x < 256) {
        __shared__ float2 fk[32];
        int s = blockIdx.x;
        if (tid < 32) fk[tid] = make_float2(fkr[s*32+tid]*scaling, fki[s*32+tid]*scaling);
        __syncthreads();
        for (int p = tid; p < 1024; p += 256) {        // p = i*64+o
            const float* kp = kern + p*32;
            float ar=0.f, ai=0.f;
            #pragma unroll
            for (int g = 0; g < 32; g++) { float kv = kp[g]; ar += kv*fk[g].x; ai += kv*fk[g].y; }
            g_psi[p*NSPEC + s] = make_float2(ar, ai);
        }
    } else {
        int k = blockIdx.x - 256;
        for (int p = tid; p < NPACK; p += 256) {
            int l = 15;
            while (c_offP[l] > p) --l;
            int r = p - c_offP[l];
            int mloc = r / (l+1);
            int nq   = r - mloc*(l+1);
            g_wig3p[k*NPACK + p] = wig3[k*NSPEC3 + c_offs[l] + mloc*(2*l+1) + (nq + l)];
            if (k == 0) {
                int sm_ = l*l + mloc;
                int sn  = l*l + nq + l;
                g_lut[p] = (sm_ << 16) | sn;
            }
        }
    }
}

// ---------------- Kernel 3: packed Fz (only n >= 0), split even/odd-i accumulators for ILP ----------------
__global__ void k_fz() {
    extern __shared__ float2 sm3[];
    float2* fh = sm3;          // [i*256+s]
    float2* ps = sm3 + 4096;   // [i*256+s]
    int bo = blockIdx.x, b = bo >> 6, o = bo & 63, tid = threadIdx.x;
    for (int p = tid; p < 4096; p += 512) {
        int i = p >> 8, s = p & 255;
        fh[p] = g_fhat[(b*16+i)*NSPEC + s];            // coalesced
        ps[p] = g_psi [(i*64+o)*NSPEC + s];            // coalesced
    }
    __syncthreads();
    for (int e = tid; e < NPACK; e += 512) {
        int lu = __ldg(&g_lut[e]);
        int sm_ = lu >> 16, sn = lu & 0xffff;
        float ar0=0.f, ai0=0.f, ar1=0.f, ai1=0.f;      // two chains, halved latency depth
        #pragma unroll
        for (int i = 0; i < 16; i += 2) {
            float2 a0 = fh[i*256 + sm_];
            float2 c0 = ps[i*256 + sn];
            float2 a1 = fh[(i+1)*256 + sm_];
            float2 c1 = ps[(i+1)*256 + sn];
            ar0 += a0.x*c0.x + a0.y*c0.y;              // fhat * conj(psi)
            ai0 += a0.y*c0.x - a0.x*c0.y;
            ar1 += a1.x*c1.x + a1.y*c1.y;
            ai1 += a1.y*c1.x - a1.x*c1.y;
        }
        g_Fz[(size_t)bo*NPACK + e] = make_float2(ar0 + ar1, ai0 + ai1);
    }
}

// ---------------- Kernel 4 (fused, Hermitian + radix-4, dual-k): spec(n>=0) + 2D synthesis ----------------
// (FROZEN: exact R7 code — 320us baseline)
// grid (1024 bo, 4 kq); each block handles 8 beta_out values, 2 at a time.
// smem float2 units: Fz 2856 | spc 1024 (2x512) | Vv 1024 (2x512) | cs16 496
// total = (2856+1024+1024+496)*8 = 43200 B -> 5 CTAs/SM
__global__ void k_main(const float* __restrict__ bias, float* __restrict__ out) {
    extern __shared__ float smraw[];
    float2* Fz   = (float2*)smraw;     // 2856
    float2* spc  = Fz  + 2856;         // 1024: [kp*512 + mi*16 + nq]
    float2* Vv   = spc + 1024;         // 1024: [kp*512 + a*16 + nq]
    float2* cs16 = Vv  + 1024;         // 496:  cs16[q*16+r] = e^{+2pi i (q-15) r/32}, r<16
    int tid = threadIdx.x;
    int bo = blockIdx.x, o = bo & 63;
    int kq = blockIdx.y;

    for (int p = tid; p < 496; p += 256) {
        int q = p >> 4, r = p & 15;
        int t = ((q-15)*r) & 31;
        float sv, cv; sincospif((float)t / 16.0f, &sv, &cv);
        cs16[p] = make_float2(cv, sv);
    }
    for (int p = tid; p < NPACK; p += 256) Fz[p] = g_Fz[(size_t)bo*NPACK + p];
    float bv = bias[o];

    int kp = tid >> 7, t2 = tid & 127;

    for (int kk4 = 0; kk4 < 4; kk4++) {
        int k = kq*8 + kk4*2 + kp;
        __syncthreads();                               // prior stage2 done before spc/Vv rewrite

        // spec[m,n] for n>=0 (half-block per k-plane), incremental packed index
        const float* wkg = g_wig3p + k*NPACK;
        for (int p = t2; p < 496; p += 128) {
            int mi = p >> 4, nq = p & 15;
            int m = mi - 15;
            int am = m < 0 ? -m : m;
            int lmin = am > nq ? am : nq;
            float ar = 0.f, ai = 0.f;
            int idx = c_offP[lmin] + (m+lmin)*(lmin+1) + nq;
            for (int l = lmin; l < 16; l++) {
                float d = __ldg(&wkg[idx]);
                float2 fz = Fz[idx];
                ar += fz.x*d;
                ai += fz.y*d;
                if (l < 15) idx += c_step[l] + m;
            }
            spc[kp*512 + p] = make_float2(ar, ai);
        }
        __syncthreads();

        // stage 1 (radix-4 over m): 31 cmacs -> V[a0], V[a0+8], V[a0+16], V[a0+24]
        {
            int a0 = t2 >> 4, n = t2 & 15;             // a0 in 0..7
            float s0r=0,s0i=0,s1r=0,s1i=0,s2r=0,s2i=0,s3r=0,s3i=0;
            #pragma unroll
            for (int mi = 0; mi < 31; mi++) {
                float2 sp = spc[kp*512 + mi*16 + n];
                float2 e  = cs16[mi*16 + a0];          // e^{+2pi i (mi-15) a0/32}
                float tr = sp.x*e.x - sp.y*e.y;
                float ti = sp.x*e.y + sp.y*e.x;
                int r = (mi + 1) & 3;                  // (mi-15) mod 4
                if      (r == 0) { s0r += tr; s0i += ti; }
                else if (r == 1) { s1r += tr; s1i += ti; }
                else if (r == 2) { s2r += tr; s2i += ti; }
                else             { s3r += tr; s3i += ti; }
            }
            float2* V = Vv + kp*512;
            V[(a0     )*16 + n] = make_float2(s0r + s1r + s2r + s3r,  s0i + s1i + s2i + s3i);
            V[(a0 +  8)*16 + n] = make_float2(s0r - s1i - s2r + s3i,  s0i + s1r - s2i - s3r);
            V[(a0 + 16)*16 + n] = make_float2(s0r - s1r + s2r - s3r,  s0i - s1i + s2i - s3i);
            V[(a0 + 24)*16 + n] = make_float2(s0r + s1i - s2r - s3i,  s0i - s1r - s2i + s3r);
        }
        __syncthreads();

        // stage 2 (radix-2 over n): out[a][g], out[a][g+16]; 4 a-values per thread
        {
            int hi = t2 >> 4, lo = t2 & 15;            // hi in 0..7, g = lo
            const float2* V = Vv + kp*512;
            size_t base = ((size_t)bo*32 + k)*1024;
            #pragma unroll
            for (int da = 0; da < 4; da++) {
                int a = hi*4 + da;
                float se = 0.f, so = 0.f;
                #pragma unroll
                for (int n = 1; n < 16; n++) {
                    float2 v = V[a*16 + n];            // broadcast
                    float2 e = cs16[(n+15)*16 + lo];   // e^{+2pi i n g/32}
                    float t = v.x*e.x - v.y*e.y;
                    if (n & 1) so += t; else se += t;
                }
                float c0 = bv + V[a*16].x;
                out[base + a*32 + lo     ] = c0 + 2.f*(se + so);
                out[base + a*32 + lo + 16] = c0 + 2.f*(se - so);
            }
        }
    }
}

extern "C" void kernel_launch(void* const* d_in, const int* in_sizes, int n_in,
                              void* d_out, int out_size) {
    const float* x       = (const float*)d_in[0];
    const float* kern    = (const float*)d_in[1];
    const float* bias    = (const float*)d_in[2];
    const float* wig_s2  = (const float*)d_in[3];
    const float* fk_re   = (const float*)d_in[4];
    const float* fk_im   = (const float*)d_in[5];
    const float* wig_so3 = (const float*)d_in[6];
    float* out = (float*)d_out;

    float scaling = 1.0f / sqrtf(32768.0f);

    cudaFuncSetAttribute(k_fz,   cudaFuncAttributeMaxDynamicSharedMemorySize, 65536);
    cudaFuncSetAttribute(k_main, cudaFuncAttributeMaxDynamicSharedMemorySize, 43200);

    k_fhat<<<dim3(16,16), 256>>>(x, wig_s2);
    k_prep<<<288, 256>>>(kern, fk_re, fk_im, scaling, wig_so3);
    k_fz  <<<1024, 512, 65536>>>();
    k_main<<<dim3(1024, 4), 256, 43200>>>(bias, out);
}